// round 11
// baseline (speedup 1.0000x reference)
#include <cuda_runtime.h>
#include <cstdint>

#define BATCH 64
#define HIN   32
#define WIN   32
#define CH    3
#define T_STEPS 2700
#define HID   128
#define PRE_N 32
#define VMAX  256
#define GATES 384
#define IN_DIM 14

// +8*GATES pad: xg prefetch pipeline overshoots by up to 2 steps at the tail
__device__ float g_xg[(size_t)BATCH * T_STEPS * GATES + 8 * GATES];
__device__ float g_hs[(size_t)BATCH * T_STEPS * HID];

__device__ __forceinline__ unsigned long long ffma2(unsigned long long a,
                                                    unsigned long long b,
                                                    unsigned long long c) {
    unsigned long long d;
    asm("fma.rn.f32x2 %0, %1, %2, %3;" : "=l"(d) : "l"(a), "l"(b), "l"(c));
    return d;
}
__device__ __forceinline__ float2 unpack2(unsigned long long v) {
    float2 f;
    asm("mov.b64 {%0, %1}, %2;" : "=f"(f.x), "=f"(f.y) : "l"(v));
    return f;
}
__device__ __forceinline__ float tanh_apx(float x) {
    float y;
    asm("tanh.approx.f32 %0, %1;" : "=f"(y) : "f"(x));
    return y;
}
__device__ __forceinline__ float sigmoid_apx(float x) {
    return fmaf(0.5f, tanh_apx(0.5f * x), 0.5f);
}
__device__ __forceinline__ float sigmoidf_fast(float x) {
    return __fdividef(1.0f, 1.0f + __expf(-x));
}

__global__ void k_dummy(int* p) { if (p) *p = 0; }

// ---------------- zero only the output border ----------------
__global__ void k_zero_border(float4* __restrict__ out4) {
    const int total = BATCH * CH * 124 * 64;
    int stride = gridDim.x * blockDim.x;
    for (int idx = blockIdx.x * blockDim.x + threadIdx.x; idx < total; idx += stride) {
        int q = idx & 63;
        int rest = idx >> 6;
        int p = rest % 124;
        int bc = rest / 124;
        int ih, iw;
        if (p < 32)      { ih = 0;       iw = p; }
        else if (p < 64) { ih = 31;      iw = p - 32; }
        else if (p < 94) { ih = p - 63;  iw = 0; }
        else             { ih = p - 93;  iw = 31; }
        out4[((size_t)(bc * HIN + ih) * WIN + iw) * 64 + q] = make_float4(0.f, 0.f, 0.f, 0.f);
    }
}

// ---------------- gather + pre MLP + input gates (b_hh folded for r,z) ----------------
__global__ __launch_bounds__(256) void k_pre(
    const float* __restrict__ x,
    const float* __restrict__ Wpre,
    const float* __restrict__ bpre,
    const float* __restrict__ Wih,
    const float* __restrict__ bih,
    const float* __restrict__ bhh)
{
    __shared__ float WihT[PRE_N * GATES];
    for (int i = threadIdx.x; i < PRE_N * GATES; i += blockDim.x) {
        int g = i >> 5, p = i & 31;
        WihT[p * GATES + g] = Wih[i];
    }
    __syncthreads();

    int warp = threadIdx.x >> 5, lane = threadIdx.x & 31;
    int row = blockIdx.x * 8 + warp;
    if (row >= BATCH * T_STEPS) return;
    int b = row / T_STEPS;
    int s = row - b * T_STEPS;
    int c  = s % 3;
    int iw = (s / 3) % 30;
    int ih = s / 90;

    float val = 0.f;
    if (lane < IN_DIM) {
        if (lane < 12) {
            int g4 = lane / 3, ch = lane % 3;
            int dy = (g4 == 3) ? 1 : 0;
            int dx = (g4 == 3) ? 0 : g4;
            val = x[(((size_t)(b * CH + ch) * HIN) + (ih + dy)) * WIN + (iw + dx)];
        } else {
            int ch = lane - 12;
            val = (c > ch)
                ? x[(((size_t)(b * CH + ch) * HIN) + (ih + 1)) * WIN + (iw + 1)]
                : -1.0f;
        }
    }

    float acc = bpre[lane];
#pragma unroll
    for (int l = 0; l < IN_DIM; l++)
        acc = fmaf(Wpre[lane * IN_DIM + l], __shfl_sync(0xffffffffu, val, l), acc);
    float pre = sigmoidf_fast(acc);

    float accs[12];
#pragma unroll
    for (int i = 0; i < 12; i++) {
        int g = i * 32 + lane;
        accs[i] = bih[g] + ((i < 8) ? bhh[g] : 0.f);
    }
#pragma unroll
    for (int p = 0; p < PRE_N; p++) {
        float pv = __shfl_sync(0xffffffffu, pre, p);
        const float* wr = &WihT[p * GATES + lane];
#pragma unroll
        for (int i = 0; i < 12; i++)
            accs[i] = fmaf(wr[i * 32], pv, accs[i]);
    }
    float* o = g_xg + (size_t)row * GATES;
#pragma unroll
    for (int i = 0; i < 12; i++) o[i * 32 + lane] = accs[i];
}

// ---------------- sequential GRU: 2 BATCHES PER CTA ----------------
// 32 CTAs; CTA b0 handles batches b0 and b0+32. 256 threads = 128 h-units x
// 2 K-slices. Weights (192 regs) are SHARED across both batches; the second
// batch only adds accumulator chains + 1 xg stream, amortizing the fixed
// per-step overhead. Post-reduction, slice role s doubles as batch role:
// s=0 finishes batch0's gates, s=1 batch1's (MUFU/STS/STG stay at 1x).
__global__ __launch_bounds__(256, 1) void k_rnn(
    const float* __restrict__ Whh,
    const float* __restrict__ bhh)
{
    int b0  = blockIdx.x;          // batches b0 and b0+32
    int tid = threadIdx.x;
    int j = tid >> 1;              // h-unit 0..127
    int s = tid & 1;               // K-slice AND batch role

    // 4 buffers of 256 floats: [batch][ping/pong]; skewed writes (gap at 64)
    __shared__ __align__(16) float h_sh[1024];

    // weights: 3 gates x 64 cols as f32x2 -> 96 ull (192 regs), shared by both batches
    unsigned long long w[96];
#pragma unroll
    for (int g = 0; g < 3; g++) {
        const ulonglong2* wp = (const ulonglong2*)(Whh + ((size_t)(g * HID + j)) * HID + 64 * s);
#pragma unroll
        for (int k = 0; k < 16; k++) {
            ulonglong2 q = wp[k];
            w[g * 32 + 2 * k]     = q.x;
            w[g * 32 + 2 * k + 1] = q.y;
        }
    }
    float bn = bhh[2 * HID + j];

    for (int i = tid; i < 1024; i += 256) h_sh[i] = 0.f;

    // xg streams: A = gate (r if s==0 else z) for BOTH batches; N = n-gate of OWN batch
    const size_t DB = (size_t)32 * T_STEPS * GATES;   // batch stride
    const float* xpA0 = g_xg + (size_t)b0 * T_STEPS * GATES + s * HID + j;
    const float* xpA1 = xpA0 + DB;
    const float* xpN  = g_xg + (size_t)(b0 + 32 * s) * T_STEPS * GATES + 2 * HID + j;
    // depth-2 pipeline, unroll x2
    float a00 = xpA0[0], a01 = xpA0[GATES];
    float a10 = xpA1[0], a11 = xpA1[GATES];
    float n0  = xpN[0],  n1  = xpN[GATES];
    xpA0 += 2 * (size_t)GATES;
    xpA1 += 2 * (size_t)GATES;
    xpN  += 2 * (size_t)GATES;

    float* hsb = g_hs + (size_t)(b0 + 32 * s) * T_STEPS * HID + j;   // own batch
    float hprev = 0.f;

    const int rbase = 68 * s;                 // read base within a buffer (floats)
    const int wofs  = j + ((j >> 6) << 2);    // skewed write offset
    const int bsel  = s << 9;                 // own batch's buffer block (0 or 512)
    __syncthreads();

    int bufofs = 0;                           // 0 or 256 floats

#define GRU_STEP(XA0, XA1, XN, OFF)                                            \
    {                                                                          \
        float xa0 = (XA0), xa1 = (XA1), xn = (XN);                             \
        (XA0) = xpA0[OFF]; (XA1) = xpA1[OFF]; (XN) = xpN[OFF];                 \
        const ulonglong2* h0 = (const ulonglong2*)(h_sh + rbase + bufofs);     \
        const ulonglong2* h1 = (const ulonglong2*)(h_sh + 512 + rbase + bufofs);\
        unsigned long long ar0 = 0ull, az0 = 0ull, an0 = 0ull;                 \
        unsigned long long ar1 = 0ull, az1 = 0ull, an1 = 0ull;                 \
        _Pragma("unroll")                                                      \
        for (int k = 0; k < 16; k++) {                                         \
            ulonglong2 q0 = h0[k];                                             \
            ulonglong2 q1 = h1[k];                                             \
            ar0 = ffma2(w[2 * k],          q0.x, ar0);                         \
            ar0 = ffma2(w[2 * k + 1],      q0.y, ar0);                         \
            az0 = ffma2(w[32 + 2 * k],     q0.x, az0);                         \
            az0 = ffma2(w[32 + 2 * k + 1], q0.y, az0);                         \
            an0 = ffma2(w[64 + 2 * k],     q0.x, an0);                         \
            an0 = ffma2(w[64 + 2 * k + 1], q0.y, an0);                         \
            ar1 = ffma2(w[2 * k],          q1.x, ar1);                         \
            ar1 = ffma2(w[2 * k + 1],      q1.y, ar1);                         \
            az1 = ffma2(w[32 + 2 * k],     q1.x, az1);                         \
            az1 = ffma2(w[32 + 2 * k + 1], q1.y, az1);                         \
            an1 = ffma2(w[64 + 2 * k],     q1.x, an1);                         \
            an1 = ffma2(w[64 + 2 * k + 1], q1.y, an1);                         \
        }                                                                      \
        float2 u;                                                              \
        u = unpack2(ar0); float pr0 = u.x + u.y;                               \
        u = unpack2(az0); float pz0 = u.x + u.y;                               \
        u = unpack2(an0); float pn0 = u.x + u.y;                               \
        u = unpack2(ar1); float pr1 = u.x + u.y;                               \
        u = unpack2(az1); float pz1 = u.x + u.y;                               \
        u = unpack2(an1); float pn1 = u.x + u.y;                               \
        if (s == 0) { pr0 += xa0; pr1 += xa1; }                                \
        else        { pz0 += xa0; pz1 += xa1; pn0 += bn; pn1 += bn; }          \
        pr0 += __shfl_xor_sync(0xffffffffu, pr0, 1);                           \
        pz0 += __shfl_xor_sync(0xffffffffu, pz0, 1);                           \
        pn0 += __shfl_xor_sync(0xffffffffu, pn0, 1);                           \
        pr1 += __shfl_xor_sync(0xffffffffu, pr1, 1);                           \
        pz1 += __shfl_xor_sync(0xffffffffu, pz1, 1);                           \
        pn1 += __shfl_xor_sync(0xffffffffu, pn1, 1);                           \
        float pr = s ? pr1 : pr0;                                              \
        float pz = s ? pz1 : pz0;                                              \
        float pn = s ? pn1 : pn0;                                              \
        float r = sigmoid_apx(pr);                                             \
        float z = sigmoid_apx(pz);                                             \
        float n = tanh_apx(fmaf(r, pn, xn));                                   \
        float hnew = fmaf(z, hprev - n, n);                                    \
        hprev = hnew;                                                          \
        bufofs ^= 256;                                                         \
        h_sh[bsel + bufofs + wofs] = hnew;    /* own batch's new buffer */     \
        hsb[0] = hnew;                                                         \
        hsb += HID;                                                            \
        __syncthreads();                                                       \
    }

    for (int t = 0; t < T_STEPS; t += 2) {   // 2700 = 1350*2
        GRU_STEP(a00, a10, n0, 0);
        GRU_STEP(a01, a11, n1, GATES);
        xpA0 += 2 * (size_t)GATES;
        xpA1 += 2 * (size_t)GATES;
        xpN  += 2 * (size_t)GATES;
    }
#undef GRU_STEP
}

// ---------------- output head GEMM + scatter (2-row ILP) ----------------
__global__ __launch_bounds__(VMAX, 1) void k_post(
    const float* __restrict__ Wpost,
    const float* __restrict__ bpost,
    float* __restrict__ out)
{
    int blk = blockIdx.x;
    int b = blk / 10;
    int s0 = (blk % 10) * 270;
    int v = threadIdx.x;

    __shared__ __align__(16) float hs_sh[30 * HID];

    unsigned long long w2[64];
    {
        const ulonglong2* wr = (const ulonglong2*)(Wpost + (size_t)v * HID);
#pragma unroll
        for (int k = 0; k < 32; k++) {
            ulonglong2 q = wr[k];
            w2[2 * k]     = q.x;
            w2[2 * k + 1] = q.y;
        }
    }
    float bias = bpost[v];
    const float* hsb = g_hs + (size_t)b * T_STEPS * HID;

    for (int tile = 0; tile < 9; tile++) {
        int sbase = s0 + tile * 30;
        __syncthreads();
        for (int i = v; i < 30 * HID; i += VMAX)
            hs_sh[i] = hsb[(size_t)sbase * HID + i];
        __syncthreads();

        for (int r = 0; r < 30; r += 2) {
            unsigned long long a0 = 0ull, a1 = 0ull, c0 = 0ull, c1 = 0ull;
            const ulonglong2* h0 = (const ulonglong2*)(hs_sh + r * HID);
            const ulonglong2* h1 = (const ulonglong2*)(hs_sh + (r + 1) * HID);
#pragma unroll
            for (int k = 0; k < 32; k++) {
                ulonglong2 q0 = h0[k];
                ulonglong2 q1 = h1[k];
                a0 = ffma2(w2[2 * k],     q0.x, a0);
                a1 = ffma2(w2[2 * k + 1], q0.y, a1);
                c0 = ffma2(w2[2 * k],     q1.x, c0);
                c1 = ffma2(w2[2 * k + 1], q1.y, c1);
            }
            float2 pa = unpack2(a0), pb = unpack2(a1);
            float o0 = (pa.x + pa.y) + (pb.x + pb.y) + bias;
            pa = unpack2(c0); pb = unpack2(c1);
            float o1 = (pa.x + pa.y) + (pb.x + pb.y) + bias;

#pragma unroll
            for (int u = 0; u < 2; u++) {
                int ss = sbase + r + u;
                int c  = ss % 3;
                int iw = (ss / 3) % 30;
                int ih = ss / 90;
                size_t idx = ((((size_t)(b * CH + c) * HIN) + (ih + 1)) * WIN + (iw + 1))
                             * (size_t)VMAX + v;
                out[idx] = u ? o1 : o0;
            }
        }
    }
}

extern "C" void kernel_launch(void* const* d_in, const int* in_sizes, int n_in,
                              void* d_out, int out_size) {
    const float* x      = (const float*)d_in[0];
    const float* W_pre  = (const float*)d_in[1];
    const float* b_pre  = (const float*)d_in[2];
    const float* W_ih   = (const float*)d_in[3];
    const float* b_ih   = (const float*)d_in[4];
    const float* W_hh   = (const float*)d_in[5];
    const float* b_hh   = (const float*)d_in[6];
    const float* W_post = (const float*)d_in[7];
    const float* b_post = (const float*)d_in[8];
    float* out = (float*)d_out;

    k_dummy<<<1, 32>>>(nullptr);
    k_zero_border<<<2976, 512>>>((float4*)out);
    k_pre<<<(BATCH * T_STEPS) / 8, 256>>>(x, W_pre, b_pre, W_ih, b_ih, b_hh);
    k_rnn<<<32, 256>>>(W_hh, b_hh);
    k_post<<<BATCH * 10, VMAX>>>(W_post, b_post, out);
}

// round 12
// speedup vs baseline: 1.3976x; 1.3976x over previous
#include <cuda_runtime.h>
#include <cstdint>

#define BATCH 64
#define HIN   32
#define WIN   32
#define CH    3
#define T_STEPS 2700
#define HID   128
#define PRE_N 32
#define VMAX  256
#define GATES 384
#define IN_DIM 14

// +8*GATES pad: xg prefetch pipeline overshoots by up to 4 steps at the tail
__device__ float g_xg[(size_t)BATCH * T_STEPS * GATES + 8 * GATES];
__device__ float g_hs[(size_t)BATCH * T_STEPS * HID];

// progress/task state for the fused rnn+post kernel (reset each replay by k_zero_border)
__device__ volatile int g_prog[BATCH];
__device__ int g_task;

__device__ __forceinline__ unsigned long long ffma2(unsigned long long a,
                                                    unsigned long long b,
                                                    unsigned long long c) {
    unsigned long long d;
    asm("fma.rn.f32x2 %0, %1, %2, %3;" : "=l"(d) : "l"(a), "l"(b), "l"(c));
    return d;
}
__device__ __forceinline__ float2 unpack2(unsigned long long v) {
    float2 f;
    asm("mov.b64 {%0, %1}, %2;" : "=f"(f.x), "=f"(f.y) : "l"(v));
    return f;
}
__device__ __forceinline__ float tanh_apx(float x) {
    float y;
    asm("tanh.approx.f32 %0, %1;" : "=f"(y) : "f"(x));
    return y;
}
__device__ __forceinline__ float sigmoid_apx(float x) {
    return fmaf(0.5f, tanh_apx(0.5f * x), 0.5f);
}
__device__ __forceinline__ float sigmoidf_fast(float x) {
    return __fdividef(1.0f, 1.0f + __expf(-x));
}

__global__ void k_dummy(int* p) { if (p) *p = 0; }

// ---------------- zero output border + reset progress flags ----------------
__global__ void k_zero_border(float4* __restrict__ out4) {
    if (blockIdx.x == 0) {
        if (threadIdx.x < BATCH) *(int*)&g_prog[threadIdx.x] = 0;
        if (threadIdx.x == BATCH) g_task = 0;
    }
    const int total = BATCH * CH * 124 * 64;
    int stride = gridDim.x * blockDim.x;
    for (int idx = blockIdx.x * blockDim.x + threadIdx.x; idx < total; idx += stride) {
        int q = idx & 63;
        int rest = idx >> 6;
        int p = rest % 124;
        int bc = rest / 124;
        int ih, iw;
        if (p < 32)      { ih = 0;       iw = p; }
        else if (p < 64) { ih = 31;      iw = p - 32; }
        else if (p < 94) { ih = p - 63;  iw = 0; }
        else             { ih = p - 93;  iw = 31; }
        out4[((size_t)(bc * HIN + ih) * WIN + iw) * 64 + q] = make_float4(0.f, 0.f, 0.f, 0.f);
    }
}

// ---------------- gather + pre MLP + input gates (b_hh folded for r,z) ----------------
__global__ __launch_bounds__(256) void k_pre(
    const float* __restrict__ x,
    const float* __restrict__ Wpre,
    const float* __restrict__ bpre,
    const float* __restrict__ Wih,
    const float* __restrict__ bih,
    const float* __restrict__ bhh)
{
    __shared__ float WihT[PRE_N * GATES];
    for (int i = threadIdx.x; i < PRE_N * GATES; i += blockDim.x) {
        int g = i >> 5, p = i & 31;
        WihT[p * GATES + g] = Wih[i];
    }
    __syncthreads();

    int warp = threadIdx.x >> 5, lane = threadIdx.x & 31;
    int row = blockIdx.x * 8 + warp;
    if (row >= BATCH * T_STEPS) return;
    int b = row / T_STEPS;
    int s = row - b * T_STEPS;
    int c  = s % 3;
    int iw = (s / 3) % 30;
    int ih = s / 90;

    float val = 0.f;
    if (lane < IN_DIM) {
        if (lane < 12) {
            int g4 = lane / 3, ch = lane % 3;
            int dy = (g4 == 3) ? 1 : 0;
            int dx = (g4 == 3) ? 0 : g4;
            val = x[(((size_t)(b * CH + ch) * HIN) + (ih + dy)) * WIN + (iw + dx)];
        } else {
            int ch = lane - 12;
            val = (c > ch)
                ? x[(((size_t)(b * CH + ch) * HIN) + (ih + 1)) * WIN + (iw + 1)]
                : -1.0f;
        }
    }

    float acc = bpre[lane];
#pragma unroll
    for (int l = 0; l < IN_DIM; l++)
        acc = fmaf(Wpre[lane * IN_DIM + l], __shfl_sync(0xffffffffu, val, l), acc);
    float pre = sigmoidf_fast(acc);

    float accs[12];
#pragma unroll
    for (int i = 0; i < 12; i++) {
        int g = i * 32 + lane;
        accs[i] = bih[g] + ((i < 8) ? bhh[g] : 0.f);
    }
#pragma unroll
    for (int p = 0; p < PRE_N; p++) {
        float pv = __shfl_sync(0xffffffffu, pre, p);
        const float* wr = &WihT[p * GATES + lane];
#pragma unroll
        for (int i = 0; i < 12; i++)
            accs[i] = fmaf(wr[i * 32], pv, accs[i]);
    }
    float* o = g_xg + (size_t)row * GATES;
#pragma unroll
    for (int i = 0; i < 12; i++) o[i * 32 + lane] = accs[i];
}

// ---------------- FUSED: rnn (CTAs 0..63) + post workers (CTAs 64..147) ----------------
// rnn = unchanged round-4 champion (512 thr = 128 units x 4 K-slices, depth-4
// xg prefetch) + progress publish every 64 steps.
// workers = persistent; pull (c-major) tasks, spin on g_prog gate, compute the
// output-head chunk with W_post split across thread halves + smem combine.
#define HSKEW 160
__global__ __launch_bounds__(512, 1) void k_fused(
    const float* __restrict__ Whh,
    const float* __restrict__ bhh,
    const float* __restrict__ Wpost,
    const float* __restrict__ bpost,
    float* __restrict__ out)
{
    __shared__ __align__(16) float smem_buf[30 * HID + 1024];  // worker: hs(3840)+psum(1024); rnn: h ping-pong
    __shared__ int sh_task;

    int tid = threadIdx.x;

    if (blockIdx.x < BATCH) {
        // ================= RNN role (round-4 champion body) =================
        int b = blockIdx.x;
        int j = tid >> 2;
        int s = tid & 3;
        float (*h_sh)[HSKEW] = (float(*)[HSKEW])smem_buf;

        unsigned long long w[3][16];
#pragma unroll
        for (int g = 0; g < 3; g++) {
            const ulonglong2* p = (const ulonglong2*)(Whh + ((size_t)(g * HID + j)) * HID + 32 * s);
#pragma unroll
            for (int k = 0; k < 8; k++) {
                ulonglong2 q = p[k];
                w[g][2 * k]     = q.x;
                w[g][2 * k + 1] = q.y;
            }
        }
        float bn = bhh[2 * HID + j];

        if (tid < HSKEW) { h_sh[0][tid] = 0.f; h_sh[1][tid] = 0.f; }

        int g0 = (s < 3) ? s : 2;
        const float* xgp = g_xg + (size_t)b * T_STEPS * GATES + g0 * HID + j;
        float x0 = xgp[0];
        float x1 = xgp[GATES];
        float x2 = xgp[2 * GATES];
        float x3 = xgp[3 * GATES];
        const float* xp = xgp + 4 * (size_t)GATES;
        float* hsb = g_hs + (size_t)b * T_STEPS * HID + j;
        float hprev = 0.f;
        int sk = (j >> 5) * 4;
        int lq = (tid & 31) & ~3;
        __syncthreads();

        int buf = 0;

#define GRU_STEP(XGC)                                                          \
    {                                                                          \
        const ulonglong2* h2 = (const ulonglong2*)(&h_sh[buf][36 * s]);        \
        unsigned long long ar = 0ull, az = 0ull, an = 0ull;                    \
        _Pragma("unroll")                                                      \
        for (int k = 0; k < 8; k++) {                                          \
            ulonglong2 q = h2[k];                                              \
            ar = ffma2(w[0][2 * k],     q.x, ar);                              \
            ar = ffma2(w[0][2 * k + 1], q.y, ar);                              \
            az = ffma2(w[1][2 * k],     q.x, az);                              \
            az = ffma2(w[1][2 * k + 1], q.y, az);                              \
            an = ffma2(w[2][2 * k],     q.x, an);                              \
            an = ffma2(w[2][2 * k + 1], q.y, an);                              \
        }                                                                      \
        float2 p;                                                              \
        p = unpack2(ar); float hr = p.x + p.y; if (s == 0) hr += (XGC);        \
        p = unpack2(az); float hz = p.x + p.y; if (s == 1) hz += (XGC);        \
        p = unpack2(an); float hn = p.x + p.y; if (s == 3) hn += bn;           \
        float xn = __shfl_sync(0xffffffffu, (XGC), lq | 2);                    \
        hr += __shfl_xor_sync(0xffffffffu, hr, 1);                             \
        hr += __shfl_xor_sync(0xffffffffu, hr, 2);                             \
        hz += __shfl_xor_sync(0xffffffffu, hz, 1);                             \
        hz += __shfl_xor_sync(0xffffffffu, hz, 2);                             \
        hn += __shfl_xor_sync(0xffffffffu, hn, 1);                             \
        hn += __shfl_xor_sync(0xffffffffu, hn, 2);                             \
        float r = sigmoid_apx(hr);                                             \
        float z = sigmoid_apx(hz);                                             \
        float n = tanh_apx(fmaf(r, hn, xn));                                   \
        float hnew = fmaf(z, hprev - n, n);                                    \
        hprev = hnew;                                                          \
        buf ^= 1;                                                              \
        if (s == 0) { h_sh[buf][j + sk] = hnew; hsb[0] = hnew; }               \
        hsb += HID;                                                            \
        __syncthreads();                                                       \
    }

        for (int t = 0; t < T_STEPS; t += 4) {
            if ((t & 63) == 0 && t != 0) {
                __threadfence();
                __syncthreads();
                if (tid == 0) g_prog[b] = t;   // hs rows < t are globally visible
            }
            float n0 = xp[0];
            float n1 = xp[GATES];
            float n2 = xp[2 * GATES];
            float n3 = xp[3 * GATES];
            xp += 4 * (size_t)GATES;
            GRU_STEP(x0); x0 = n0;
            GRU_STEP(x1); x1 = n1;
            GRU_STEP(x2); x2 = n2;
            GRU_STEP(x3); x3 = n3;
        }
#undef GRU_STEP
        __threadfence();
        __syncthreads();
        if (tid == 0) g_prog[b] = T_STEPS;
    } else {
        // ================= POST worker role =================
        float* hs_sh = smem_buf;            // 3840 floats
        float* psum  = smem_buf + 30 * HID; // 1024 floats
        int v    = tid & 255;
        int half = tid >> 8;                // K-half: cols [64*half, 64*half+64)

        unsigned long long w2[32];
        {
            const ulonglong2* wr = (const ulonglong2*)(Wpost + (size_t)v * HID + 64 * half);
#pragma unroll
            for (int k = 0; k < 16; k++) {
                ulonglong2 q = wr[k];
                w2[2 * k]     = q.x;
                w2[2 * k + 1] = q.y;
            }
        }
        float bias = bpost[v];

        for (;;) {
            __syncthreads();
            if (tid == 0) sh_task = atomicAdd(&g_task, 1);
            __syncthreads();
            int tau = sh_task;
            if (tau >= 640) break;
            int c = tau >> 6;          // c-major: gates open in task order
            int b = tau & 63;
            int need = (c + 1) * 270;
            if (tid == 0) {
                while (g_prog[b] < need) __nanosleep(1024);
            }
            __syncthreads();
            __threadfence();           // acquire side

            const float* hsb = g_hs + (size_t)b * T_STEPS * HID;
            int s0 = c * 270;
            for (int tile = 0; tile < 9; tile++) {
                int sbase = s0 + tile * 30;
                __syncthreads();
                for (int i = tid; i < 30 * HID; i += 512)
                    hs_sh[i] = hsb[(size_t)sbase * HID + i];
                __syncthreads();

                for (int r = 0; r < 30; r += 2) {
                    const ulonglong2* h0 = (const ulonglong2*)(hs_sh + r * HID + 64 * half);
                    const ulonglong2* h1 = (const ulonglong2*)(hs_sh + (r + 1) * HID + 64 * half);
                    unsigned long long a0 = 0ull, a1 = 0ull, c0 = 0ull, c1 = 0ull;
#pragma unroll
                    for (int k = 0; k < 16; k++) {
                        ulonglong2 q0 = h0[k];
                        ulonglong2 q1 = h1[k];
                        a0 = ffma2(w2[2 * k],     q0.x, a0);
                        a1 = ffma2(w2[2 * k + 1], q0.y, a1);
                        c0 = ffma2(w2[2 * k],     q1.x, c0);
                        c1 = ffma2(w2[2 * k + 1], q1.y, c1);
                    }
                    float2 pa = unpack2(a0), pb = unpack2(a1);
                    float o0 = (pa.x + pa.y) + (pb.x + pb.y);
                    pa = unpack2(c0); pb = unpack2(c1);
                    float o1 = (pa.x + pa.y) + (pb.x + pb.y);
                    psum[tid] = o0;
                    psum[512 + tid] = o1;
                    __syncthreads();
                    if (half == 0) {
                        float f0 = psum[tid] + psum[tid + 256] + bias;
                        float f1 = psum[512 + tid] + psum[512 + tid + 256] + bias;
#pragma unroll
                        for (int u = 0; u < 2; u++) {
                            int ss = sbase + r + u;
                            int cc = ss % 3;
                            int iw = (ss / 3) % 30;
                            int ih = ss / 90;
                            size_t idx = ((((size_t)(b * CH + cc) * HIN) + (ih + 1)) * WIN + (iw + 1))
                                         * (size_t)VMAX + v;
                            out[idx] = u ? f1 : f0;
                        }
                    }
                    __syncthreads();
                }
            }
        }
    }
}

extern "C" void kernel_launch(void* const* d_in, const int* in_sizes, int n_in,
                              void* d_out, int out_size) {
    const float* x      = (const float*)d_in[0];
    const float* W_pre  = (const float*)d_in[1];
    const float* b_pre  = (const float*)d_in[2];
    const float* W_ih   = (const float*)d_in[3];
    const float* b_ih   = (const float*)d_in[4];
    const float* W_hh   = (const float*)d_in[5];
    const float* b_hh   = (const float*)d_in[6];
    const float* W_post = (const float*)d_in[7];
    const float* b_post = (const float*)d_in[8];
    float* out = (float*)d_out;

    k_dummy<<<1, 32>>>(nullptr);
    k_zero_border<<<2976, 512>>>((float4*)out);     // also resets g_prog/g_task
    k_pre<<<(BATCH * T_STEPS) / 8, 256>>>(x, W_pre, b_pre, W_ih, b_ih, b_hh);
    k_fused<<<148, 512>>>(W_hh, b_hh, W_post, b_post, out);
}

// round 13
// speedup vs baseline: 2.3442x; 1.6774x over previous
#include <cuda_runtime.h>
#include <cstdint>

#define BATCH 64
#define HIN   32
#define WIN   32
#define CH    3
#define T_STEPS 2700
#define HID   128
#define PRE_N 32
#define VMAX  256
#define GATES 384
#define IN_DIM 14

#define NT_PRE   1280          // 64 batches x 20 chunks of 135 steps
#define NT_ZERO  96
#define NT_POST  640           // 64 batches x 10 chunks of 270 rows
#define NT_TOTAL (NT_PRE + NT_ZERO + NT_POST)
#define Z4_PER   15872         // 64*3*124*64 / 96

// +8*GATES pad: xg prefetch pipeline overshoots by up to 4 steps at the tail
__device__ float g_xg[(size_t)BATCH * T_STEPS * GATES + 8 * GATES];
__device__ float g_hs[(size_t)BATCH * T_STEPS * HID];

// cross-CTA state (reset each replay by k_reset)
__device__ volatile int g_prog[BATCH];           // rnn progress (rows) per batch
__device__ volatile int g_preflag[BATCH * 20];   // pre chunk-done flags
__device__ int g_task;                           // worker task counter

__device__ __forceinline__ unsigned long long ffma2(unsigned long long a,
                                                    unsigned long long b,
                                                    unsigned long long c) {
    unsigned long long d;
    asm("fma.rn.f32x2 %0, %1, %2, %3;" : "=l"(d) : "l"(a), "l"(b), "l"(c));
    return d;
}
__device__ __forceinline__ float2 unpack2(unsigned long long v) {
    float2 f;
    asm("mov.b64 {%0, %1}, %2;" : "=f"(f.x), "=f"(f.y) : "l"(v));
    return f;
}
__device__ __forceinline__ float tanh_apx(float x) {
    float y;
    asm("tanh.approx.f32 %0, %1;" : "=f"(y) : "f"(x));
    return y;
}
__device__ __forceinline__ float sigmoid_apx(float x) {
    return fmaf(0.5f, tanh_apx(0.5f * x), 0.5f);
}
__device__ __forceinline__ float sigmoidf_fast(float x) {
    return __fdividef(1.0f, 1.0f + __expf(-x));
}

__global__ void k_dummy(int* p) { if (p) *p = 0; }

// ---------------- reset cross-CTA state ----------------
__global__ void k_reset() {
    int i = blockIdx.x * blockDim.x + threadIdx.x;
    if (i < BATCH) *(int*)&g_prog[i] = 0;
    if (i == BATCH) g_task = 0;
    for (int k = i; k < BATCH * 20; k += gridDim.x * blockDim.x)
        *(int*)&g_preflag[k] = 0;
}

// ---------------- FUSED everything ----------------
// CTAs 0..63   : rnn for batch b (round-4 champion body), gated on pre-chunk
//                flags, publishing hs progress every 64 steps.
// CTAs 64..147 : persistent workers. Task counter phases:
//                [0,1280)   pre: gather+preMLP+input-gates for (chunk,batch)
//                [1280,1376) zero the output border
//                [1376,2016) post: output-head chunk gated on rnn progress
#define HSKEW 160
__global__ __launch_bounds__(512, 1) void k_fused(
    const float* __restrict__ x,
    const float* __restrict__ Wpre,
    const float* __restrict__ bpre,
    const float* __restrict__ Wih,
    const float* __restrict__ bih,
    const float* __restrict__ Whh,
    const float* __restrict__ bhh,
    const float* __restrict__ Wpost,
    const float* __restrict__ bpost,
    float* __restrict__ out)
{
    __shared__ __align__(16) float smem_buf[PRE_N * GATES];  // 48KB: WihT | hs+psum | rnn h
    __shared__ int sh_task;

    int tid = threadIdx.x;

    if (blockIdx.x < BATCH) {
        // ================= RNN role =================
        int b = blockIdx.x;
        int j = tid >> 2;
        int s = tid & 3;
        float (*h_sh)[HSKEW] = (float(*)[HSKEW])smem_buf;

        unsigned long long w[3][16];
#pragma unroll
        for (int g = 0; g < 3; g++) {
            const ulonglong2* p = (const ulonglong2*)(Whh + ((size_t)(g * HID + j)) * HID + 32 * s);
#pragma unroll
            for (int k = 0; k < 8; k++) {
                ulonglong2 q = p[k];
                w[g][2 * k]     = q.x;
                w[g][2 * k + 1] = q.y;
            }
        }
        float bn = bhh[2 * HID + j];

        if (tid < HSKEW) { h_sh[0][tid] = 0.f; h_sh[1][tid] = 0.f; }

        // gate: chunk 0 of this batch must be written before first xg loads
        if (tid == 0) {
            while (!g_preflag[b * 20]) __nanosleep(512);
        }
        __syncthreads();
        __threadfence();
        int nextchk = 1;

        int g0 = (s < 3) ? s : 2;
        const float* xgp = g_xg + (size_t)b * T_STEPS * GATES + g0 * HID + j;
        float x0 = xgp[0];
        float x1 = xgp[GATES];
        float x2 = xgp[2 * GATES];
        float x3 = xgp[3 * GATES];
        const float* xp = xgp + 4 * (size_t)GATES;
        float* hsb = g_hs + (size_t)b * T_STEPS * HID + j;
        float hprev = 0.f;
        int sk = (j >> 5) * 4;
        int lq = (tid & 31) & ~3;
        __syncthreads();

        int buf = 0;

#define GRU_STEP(XGC)                                                          \
    {                                                                          \
        const ulonglong2* h2 = (const ulonglong2*)(&h_sh[buf][36 * s]);        \
        unsigned long long ar = 0ull, az = 0ull, an = 0ull;                    \
        _Pragma("unroll")                                                      \
        for (int k = 0; k < 8; k++) {                                          \
            ulonglong2 q = h2[k];                                              \
            ar = ffma2(w[0][2 * k],     q.x, ar);                              \
            ar = ffma2(w[0][2 * k + 1], q.y, ar);                              \
            az = ffma2(w[1][2 * k],     q.x, az);                              \
            az = ffma2(w[1][2 * k + 1], q.y, az);                              \
            an = ffma2(w[2][2 * k],     q.x, an);                              \
            an = ffma2(w[2][2 * k + 1], q.y, an);                              \
        }                                                                      \
        float2 p;                                                              \
        p = unpack2(ar); float hr = p.x + p.y; if (s == 0) hr += (XGC);        \
        p = unpack2(az); float hz = p.x + p.y; if (s == 1) hz += (XGC);        \
        p = unpack2(an); float hn = p.x + p.y; if (s == 3) hn += bn;           \
        float xn = __shfl_sync(0xffffffffu, (XGC), lq | 2);                    \
        hr += __shfl_xor_sync(0xffffffffu, hr, 1);                             \
        hr += __shfl_xor_sync(0xffffffffu, hr, 2);                             \
        hz += __shfl_xor_sync(0xffffffffu, hz, 1);                             \
        hz += __shfl_xor_sync(0xffffffffu, hz, 2);                             \
        hn += __shfl_xor_sync(0xffffffffu, hn, 1);                             \
        hn += __shfl_xor_sync(0xffffffffu, hn, 2);                             \
        float r = sigmoid_apx(hr);                                             \
        float z = sigmoid_apx(hz);                                             \
        float n = tanh_apx(fmaf(r, hn, xn));                                   \
        float hnew = fmaf(z, hprev - n, n);                                    \
        hprev = hnew;                                                          \
        buf ^= 1;                                                              \
        if (s == 0) { h_sh[buf][j + sk] = hnew; hsb[0] = hnew; }               \
        hsb += HID;                                                            \
        __syncthreads();                                                       \
    }

        for (int t = 0; t < T_STEPS; t += 4) {
            if ((t & 63) == 0 && t != 0) {
                __threadfence();               // release hs rows < t
                __syncthreads();
                if (tid == 0) {
                    g_prog[b] = t;
                    int tcneed = (t + 67) / 135;
                    if (tcneed > 19) tcneed = 19;
                    while (nextchk <= tcneed) {
                        if (g_preflag[b * 20 + nextchk]) nextchk++;
                        else __nanosleep(512);
                    }
                }
                __syncthreads();
                __threadfence();               // acquire xg rows
            }
            float n0 = xp[0];
            float n1 = xp[GATES];
            float n2 = xp[2 * GATES];
            float n3 = xp[3 * GATES];
            xp += 4 * (size_t)GATES;
            GRU_STEP(x0); x0 = n0;
            GRU_STEP(x1); x1 = n1;
            GRU_STEP(x2); x2 = n2;
            GRU_STEP(x3); x3 = n3;
        }
#undef GRU_STEP
        __threadfence();
        __syncthreads();
        if (tid == 0) g_prog[b] = T_STEPS;
    } else {
        // ================= WORKER role =================
        float* WihT  = smem_buf;             // pre phase (12288 floats)
        float* hs_sh = smem_buf;             // post phase (3840 floats)
        float* psum  = smem_buf + 30 * HID;  // post phase (1024 floats)
        int warp = tid >> 5, lane = tid & 31;

        // preload WihT for the pre phase
        for (int i = tid; i < PRE_N * GATES; i += 512) {
            int g = i >> 5, p = i & 31;
            WihT[p * GATES + g] = Wih[i];
        }
        __syncthreads();

        // post-role constants
        int v    = tid & 255;
        int half = tid >> 8;
        unsigned long long w2[32];
        {
            const ulonglong2* wr = (const ulonglong2*)(Wpost + (size_t)v * HID + 64 * half);
#pragma unroll
            for (int k = 0; k < 16; k++) {
                ulonglong2 q = wr[k];
                w2[2 * k]     = q.x;
                w2[2 * k + 1] = q.y;
            }
        }
        float bias = bpost[v];

        for (;;) {
            __syncthreads();
            if (tid == 0) sh_task = atomicAdd(&g_task, 1);
            __syncthreads();
            int tau = sh_task;
            if (tau >= NT_TOTAL) break;

            if (tau < NT_PRE) {
                // ---- PRE task: chunk tc (135 steps) of batch b ----
                int tc = tau >> 6;
                int b  = tau & 63;
                int sbase = tc * 135;
                for (int rr = warp; rr < 135; rr += 16) {
                    int s = sbase + rr;
                    int c  = s % 3;
                    int iw = (s / 3) % 30;
                    int ih = s / 90;

                    float val = 0.f;
                    if (lane < IN_DIM) {
                        if (lane < 12) {
                            int g4 = lane / 3, ch = lane % 3;
                            int dy = (g4 == 3) ? 1 : 0;
                            int dx = (g4 == 3) ? 0 : g4;
                            val = x[(((size_t)(b * CH + ch) * HIN) + (ih + dy)) * WIN + (iw + dx)];
                        } else {
                            int ch = lane - 12;
                            val = (c > ch)
                                ? x[(((size_t)(b * CH + ch) * HIN) + (ih + 1)) * WIN + (iw + 1)]
                                : -1.0f;
                        }
                    }

                    float acc = bpre[lane];
#pragma unroll
                    for (int l = 0; l < IN_DIM; l++)
                        acc = fmaf(Wpre[lane * IN_DIM + l], __shfl_sync(0xffffffffu, val, l), acc);
                    float pre = sigmoidf_fast(acc);

                    float accs[12];
#pragma unroll
                    for (int i = 0; i < 12; i++) {
                        int g = i * 32 + lane;
                        accs[i] = bih[g] + ((i < 8) ? bhh[g] : 0.f);
                    }
#pragma unroll
                    for (int p = 0; p < PRE_N; p++) {
                        float pv = __shfl_sync(0xffffffffu, pre, p);
                        const float* wr = &WihT[p * GATES + lane];
#pragma unroll
                        for (int i = 0; i < 12; i++)
                            accs[i] = fmaf(wr[i * 32], pv, accs[i]);
                    }
                    float* o = g_xg + ((size_t)b * T_STEPS + s) * GATES;
#pragma unroll
                    for (int i = 0; i < 12; i++) o[i * 32 + lane] = accs[i];
                }
                __threadfence();
                __syncthreads();
                if (tid == 0) g_preflag[b * 20 + tc] = 1;
            } else if (tau < NT_PRE + NT_ZERO) {
                // ---- ZERO task: slice of the output border ----
                int z = tau - NT_PRE;
                float4* out4 = (float4*)out;
                int end = (z + 1) * Z4_PER;
                for (int idx = z * Z4_PER + tid; idx < end; idx += 512) {
                    int q = idx & 63;
                    int rest = idx >> 6;
                    int p = rest % 124;
                    int bc = rest / 124;
                    int ih, iw;
                    if (p < 32)      { ih = 0;       iw = p; }
                    else if (p < 64) { ih = 31;      iw = p - 32; }
                    else if (p < 94) { ih = p - 63;  iw = 0; }
                    else             { ih = p - 93;  iw = 31; }
                    out4[((size_t)(bc * HIN + ih) * WIN + iw) * 64 + q] =
                        make_float4(0.f, 0.f, 0.f, 0.f);
                }
            } else {
                // ---- POST task: 270-row output-head chunk, gated on rnn ----
                int pt = tau - NT_PRE - NT_ZERO;
                int c = pt >> 6;       // c-major: gates open in task order
                int b = pt & 63;
                int need = (c + 1) * 270;
                if (tid == 0) {
                    while (g_prog[b] < need) __nanosleep(1024);
                }
                __syncthreads();
                __threadfence();       // acquire hs

                const float* hsb = g_hs + (size_t)b * T_STEPS * HID;
                int s0 = c * 270;
                for (int tile = 0; tile < 9; tile++) {
                    int sbase = s0 + tile * 30;
                    __syncthreads();
                    for (int i = tid; i < 30 * HID; i += 512)
                        hs_sh[i] = hsb[(size_t)sbase * HID + i];
                    __syncthreads();

                    for (int r = 0; r < 30; r += 2) {
                        const ulonglong2* h0 = (const ulonglong2*)(hs_sh + r * HID + 64 * half);
                        const ulonglong2* h1 = (const ulonglong2*)(hs_sh + (r + 1) * HID + 64 * half);
                        unsigned long long a0 = 0ull, a1 = 0ull, c0 = 0ull, c1 = 0ull;
#pragma unroll
                        for (int k = 0; k < 16; k++) {
                            ulonglong2 q0 = h0[k];
                            ulonglong2 q1 = h1[k];
                            a0 = ffma2(w2[2 * k],     q0.x, a0);
                            a1 = ffma2(w2[2 * k + 1], q0.y, a1);
                            c0 = ffma2(w2[2 * k],     q1.x, c0);
                            c1 = ffma2(w2[2 * k + 1], q1.y, c1);
                        }
                        float2 pa = unpack2(a0), pb = unpack2(a1);
                        float o0 = (pa.x + pa.y) + (pb.x + pb.y);
                        pa = unpack2(c0); pb = unpack2(c1);
                        float o1 = (pa.x + pa.y) + (pb.x + pb.y);
                        psum[tid] = o0;
                        psum[512 + tid] = o1;
                        __syncthreads();
                        if (half == 0) {
                            float f0 = psum[tid] + psum[tid + 256] + bias;
                            float f1 = psum[512 + tid] + psum[512 + tid + 256] + bias;
#pragma unroll
                            for (int u = 0; u < 2; u++) {
                                int ss = sbase + r + u;
                                int cc = ss % 3;
                                int iw = (ss / 3) % 30;
                                int ih = ss / 90;
                                size_t idx = ((((size_t)(b * CH + cc) * HIN) + (ih + 1)) * WIN + (iw + 1))
                                             * (size_t)VMAX + v;
                                out[idx] = u ? f1 : f0;
                            }
                        }
                        __syncthreads();
                    }
                }
            }
        }
    }
}

extern "C" void kernel_launch(void* const* d_in, const int* in_sizes, int n_in,
                              void* d_out, int out_size) {
    const float* x      = (const float*)d_in[0];
    const float* W_pre  = (const float*)d_in[1];
    const float* b_pre  = (const float*)d_in[2];
    const float* W_ih   = (const float*)d_in[3];
    const float* b_ih   = (const float*)d_in[4];
    const float* W_hh   = (const float*)d_in[5];
    const float* b_hh   = (const float*)d_in[6];
    const float* W_post = (const float*)d_in[7];
    const float* b_post = (const float*)d_in[8];
    float* out = (float*)d_out;

    k_dummy<<<1, 32>>>(nullptr);
    k_reset<<<4, 512>>>();
    k_fused<<<148, 512>>>(x, W_pre, b_pre, W_ih, b_ih,
                          W_hh, b_hh, W_post, b_post, out);
}